// round 14
// baseline (speedup 1.0000x reference)
#include <cuda_runtime.h>
#include <stdint.h>

// ---------------------------------------------------------------------------
// PairLoss: result = ( sum_{gt<0.5} exp(p) * sum_{gt>0.5} exp(-p) - n_neg ) / 2
//
// Streaming reduction over 2 x 128MB fp32. Measured gradient: fewer/larger
// CTAs -> higher BW (1184x256: 5.87, 592x512: 5.96, 296x1024: 6.08 TB/s,
// identical access pattern). At 2 CTAs/SM, unroll x2 keeps oe*MLP_p1 = 8
// below the cross-CTA L1tex contention knee (16) that caused the R5
// regression at 8 CTAs/SM -> now safe to double in-flight bytes.
//
// Deterministic (fixed-order fp64 final combine in last-arriving block),
// graph-capturable, allocation-free.
// ---------------------------------------------------------------------------

#define NBLOCKS 296
#define NTHREADS 1024

__device__ double g_part[3 * NBLOCKS];
__device__ unsigned int g_done = 0;   // self-resetting arrival counter

__device__ __forceinline__ void accum_one(float p, float g, float& s_neg,
                                          float& s_pos, float& cnt) {
    bool pos = g > 0.5f;
    float e = __expf(pos ? -p : p);
    if (pos) s_pos += e;
    else { s_neg += e; cnt += 1.0f; }
}

__device__ __forceinline__ void accum4(const float4& p, const float4& g,
                                       float& s_neg, float& s_pos, float& cnt) {
    accum_one(p.x, g.x, s_neg, s_pos, cnt);
    accum_one(p.y, g.y, s_neg, s_pos, cnt);
    accum_one(p.z, g.z, s_neg, s_pos, cnt);
    accum_one(p.w, g.w, s_neg, s_pos, cnt);
}

// Reduce three values across the block; results valid on (warp 0, lane 0).
template <typename T>
__device__ __forceinline__ void block_reduce3(T& a, T& b, T& c, T* sh) {
    int lane = threadIdx.x & 31;
    int warp = threadIdx.x >> 5;
    const int nw = NTHREADS / 32;

    #pragma unroll
    for (int off = 16; off > 0; off >>= 1) {
        a += __shfl_down_sync(0xffffffffu, a, off);
        b += __shfl_down_sync(0xffffffffu, b, off);
        c += __shfl_down_sync(0xffffffffu, c, off);
    }
    if (lane == 0) { sh[warp] = a; sh[nw + warp] = b; sh[2 * nw + warp] = c; }
    __syncthreads();
    if (warp == 0) {
        a = (lane < nw) ? sh[lane] : (T)0;
        b = (lane < nw) ? sh[nw + lane] : (T)0;
        c = (lane < nw) ? sh[2 * nw + lane] : (T)0;
        #pragma unroll
        for (int off = 16; off > 0; off >>= 1) {
            a += __shfl_down_sync(0xffffffffu, a, off);
            b += __shfl_down_sync(0xffffffffu, b, off);
            c += __shfl_down_sync(0xffffffffu, c, off);
        }
    }
}

__device__ __forceinline__ void epilogue(float s_neg, float s_pos, float cnt,
                                         float* __restrict__ out) {
    __shared__ float shf[3 * (NTHREADS / 32)];
    block_reduce3(s_neg, s_pos, cnt, shf);

    __shared__ bool s_last;
    if (threadIdx.x == 0) {
        g_part[blockIdx.x]               = (double)s_neg;
        g_part[NBLOCKS + blockIdx.x]     = (double)s_pos;
        g_part[2 * NBLOCKS + blockIdx.x] = (double)cnt;
        __threadfence();
        unsigned int prev = atomicAdd(&g_done, 1u);
        s_last = (prev == (unsigned int)(gridDim.x - 1));
    }
    __syncthreads();

    if (s_last) {
        __threadfence();  // acquire: all blocks' partials now visible
        double a = 0.0, b = 0.0, c = 0.0;
        for (int k = threadIdx.x; k < NBLOCKS; k += NTHREADS) {
            a += g_part[k];
            b += g_part[NBLOCKS + k];
            c += g_part[2 * NBLOCKS + k];
        }
        __shared__ double shd[3 * (NTHREADS / 32)];
        block_reduce3(a, b, c, shd);
        if (threadIdx.x == 0) {
            out[0] = (float)((a * b - c) * 0.5);
            g_done = 0;  // reset for next graph replay
        }
    }
}

__global__ void __launch_bounds__(NTHREADS)
pairloss_stream(const float4* __restrict__ p4, const float4* __restrict__ g4,
                const float* __restrict__ pred, const float* __restrict__ gt,
                int n, float* __restrict__ out) {
    float s_neg = 0.0f, s_pos = 0.0f, cnt = 0.0f;
    const int n4 = n >> 2;
    const int stride = gridDim.x * blockDim.x;
    int i = blockIdx.x * blockDim.x + threadIdx.x;

    // x2-unrolled grid-stride: 4 independent streaming LDG.128 in flight.
    for (; i + stride < n4; i += 2 * stride) {
        float4 pa = __ldcs(p4 + i);
        float4 ga = __ldcs(g4 + i);
        float4 pb = __ldcs(p4 + i + stride);
        float4 gb = __ldcs(g4 + i + stride);
        accum4(pa, ga, s_neg, s_pos, cnt);
        accum4(pb, gb, s_neg, s_pos, cnt);
    }
    if (i < n4) {
        float4 p = __ldcs(p4 + i);
        float4 g = __ldcs(g4 + i);
        accum4(p, g, s_neg, s_pos, cnt);
    }
    // scalar tail (n % 4)
    for (int t = (n4 << 2) + blockIdx.x * blockDim.x + threadIdx.x; t < n;
         t += stride) {
        accum_one(__ldcs(pred + t), __ldcs(gt + t), s_neg, s_pos, cnt);
    }

    epilogue(s_neg, s_pos, cnt, out);
}

// Scalar fallback for unaligned inputs (not expected from the harness).
__global__ void __launch_bounds__(NTHREADS)
pairloss_scalar(const float* __restrict__ pred, const float* __restrict__ gt,
                int n, float* __restrict__ out) {
    float s_neg = 0.0f, s_pos = 0.0f, cnt = 0.0f;
    int stride = gridDim.x * blockDim.x;
    for (int i = blockIdx.x * blockDim.x + threadIdx.x; i < n; i += stride)
        accum_one(pred[i], gt[i], s_neg, s_pos, cnt);
    epilogue(s_neg, s_pos, cnt, out);
}

extern "C" void kernel_launch(void* const* d_in, const int* in_sizes, int n_in,
                              void* d_out, int out_size) {
    const float* pred = (const float*)d_in[0];
    const float* gt   = (const float*)d_in[1];
    float* out = (float*)d_out;
    int n = in_sizes[0];

    bool aligned = (((uintptr_t)pred | (uintptr_t)gt) & 0xF) == 0;
    if (aligned) {
        pairloss_stream<<<NBLOCKS, NTHREADS>>>(
            (const float4*)pred, (const float4*)gt, pred, gt, n, out);
    } else {
        pairloss_scalar<<<NBLOCKS, NTHREADS>>>(pred, gt, n, out);
    }
}

// round 15
// speedup vs baseline: 1.0138x; 1.0138x over previous
#include <cuda_runtime.h>
#include <stdint.h>

// ---------------------------------------------------------------------------
// PairLoss: result = ( sum_{gt<0.5} exp(p) * sum_{gt>0.5} exp(-p) - n_neg ) / 2
//
// FINAL CONFIGURATION (R13, re-benched for stability).
// Streaming reduction over 2 x 128MB fp32. Design-space findings:
//  - load mechanism: plain x1 grid-stride LDG.128 (__ldcs) beats LDG.128x2,
//    LDG.E.256, and cp.async pipelines (all regress or neutral).
//  - CTA shape: consolidation at constant 2048 thr/SM is the only positive
//    gradient: 1184x256=5.87, 592x512=5.96, 296x1024=6.08 TB/s. 296x1024
//    (2 CTA/SM, one exact wave) is the endpoint (1024 = max block).
//  - body runs within ~0.6us of its achieved-BW floor; fused last-block
//    combine keeps total overhead ~0.7us.
//
// Deterministic (fixed-order fp64 final combine in last-arriving block),
// graph-capturable, allocation-free.
// ---------------------------------------------------------------------------

#define NBLOCKS 296
#define NTHREADS 1024

__device__ double g_part[3 * NBLOCKS];
__device__ unsigned int g_done = 0;   // self-resetting arrival counter

__device__ __forceinline__ void accum_one(float p, float g, float& s_neg,
                                          float& s_pos, float& cnt) {
    bool pos = g > 0.5f;
    float e = __expf(pos ? -p : p);
    if (pos) s_pos += e;
    else { s_neg += e; cnt += 1.0f; }
}

// Reduce three values across the block; results valid on (warp 0, lane 0).
template <typename T>
__device__ __forceinline__ void block_reduce3(T& a, T& b, T& c, T* sh) {
    int lane = threadIdx.x & 31;
    int warp = threadIdx.x >> 5;
    const int nw = NTHREADS / 32;

    #pragma unroll
    for (int off = 16; off > 0; off >>= 1) {
        a += __shfl_down_sync(0xffffffffu, a, off);
        b += __shfl_down_sync(0xffffffffu, b, off);
        c += __shfl_down_sync(0xffffffffu, c, off);
    }
    if (lane == 0) { sh[warp] = a; sh[nw + warp] = b; sh[2 * nw + warp] = c; }
    __syncthreads();
    if (warp == 0) {
        a = (lane < nw) ? sh[lane] : (T)0;
        b = (lane < nw) ? sh[nw + lane] : (T)0;
        c = (lane < nw) ? sh[2 * nw + lane] : (T)0;
        #pragma unroll
        for (int off = 16; off > 0; off >>= 1) {
            a += __shfl_down_sync(0xffffffffu, a, off);
            b += __shfl_down_sync(0xffffffffu, b, off);
            c += __shfl_down_sync(0xffffffffu, c, off);
        }
    }
}

__device__ __forceinline__ void epilogue(float s_neg, float s_pos, float cnt,
                                         float* __restrict__ out) {
    __shared__ float shf[3 * (NTHREADS / 32)];
    block_reduce3(s_neg, s_pos, cnt, shf);

    __shared__ bool s_last;
    if (threadIdx.x == 0) {
        g_part[blockIdx.x]               = (double)s_neg;
        g_part[NBLOCKS + blockIdx.x]     = (double)s_pos;
        g_part[2 * NBLOCKS + blockIdx.x] = (double)cnt;
        __threadfence();
        unsigned int prev = atomicAdd(&g_done, 1u);
        s_last = (prev == (unsigned int)(gridDim.x - 1));
    }
    __syncthreads();

    if (s_last) {
        __threadfence();  // acquire: all blocks' partials now visible
        // 296 partials x3: single strided read per thread; L2-hot.
        double a = 0.0, b = 0.0, c = 0.0;
        for (int k = threadIdx.x; k < NBLOCKS; k += NTHREADS) {
            a += g_part[k];
            b += g_part[NBLOCKS + k];
            c += g_part[2 * NBLOCKS + k];
        }
        __shared__ double shd[3 * (NTHREADS / 32)];
        block_reduce3(a, b, c, shd);
        if (threadIdx.x == 0) {
            out[0] = (float)((a * b - c) * 0.5);
            g_done = 0;  // reset for next graph replay
        }
    }
}

__global__ void __launch_bounds__(NTHREADS)
pairloss_stream(const float4* __restrict__ p4, const float4* __restrict__ g4,
                const float* __restrict__ pred, const float* __restrict__ gt,
                int n, float* __restrict__ out) {
    float s_neg = 0.0f, s_pos = 0.0f, cnt = 0.0f;
    const int n4 = n >> 2;
    const int stride = gridDim.x * blockDim.x;

    // x1 grid-stride, streaming loads (evict-first; one-touch data).
    for (int i = blockIdx.x * blockDim.x + threadIdx.x; i < n4; i += stride) {
        float4 p = __ldcs(p4 + i);
        float4 g = __ldcs(g4 + i);
        accum_one(p.x, g.x, s_neg, s_pos, cnt);
        accum_one(p.y, g.y, s_neg, s_pos, cnt);
        accum_one(p.z, g.z, s_neg, s_pos, cnt);
        accum_one(p.w, g.w, s_neg, s_pos, cnt);
    }
    // scalar tail (n % 4)
    for (int t = (n4 << 2) + blockIdx.x * blockDim.x + threadIdx.x; t < n;
         t += stride) {
        accum_one(__ldcs(pred + t), __ldcs(gt + t), s_neg, s_pos, cnt);
    }

    epilogue(s_neg, s_pos, cnt, out);
}

// Scalar fallback for unaligned inputs (not expected from the harness).
__global__ void __launch_bounds__(NTHREADS)
pairloss_scalar(const float* __restrict__ pred, const float* __restrict__ gt,
                int n, float* __restrict__ out) {
    float s_neg = 0.0f, s_pos = 0.0f, cnt = 0.0f;
    int stride = gridDim.x * blockDim.x;
    for (int i = blockIdx.x * blockDim.x + threadIdx.x; i < n; i += stride)
        accum_one(pred[i], gt[i], s_neg, s_pos, cnt);
    epilogue(s_neg, s_pos, cnt, out);
}

extern "C" void kernel_launch(void* const* d_in, const int* in_sizes, int n_in,
                              void* d_out, int out_size) {
    const float* pred = (const float*)d_in[0];
    const float* gt   = (const float*)d_in[1];
    float* out = (float*)d_out;
    int n = in_sizes[0];

    bool aligned = (((uintptr_t)pred | (uintptr_t)gt) & 0xF) == 0;
    if (aligned) {
        pairloss_stream<<<NBLOCKS, NTHREADS>>>(
            (const float4*)pred, (const float4*)gt, pred, gt, n, out);
    } else {
        pairloss_scalar<<<NBLOCKS, NTHREADS>>>(pred, gt, n, out);
    }
}

// round 16
// speedup vs baseline: 1.0330x; 1.0190x over previous
#include <cuda_runtime.h>
#include <stdint.h>

// ---------------------------------------------------------------------------
// PairLoss: result = ( sum_{gt<0.5} exp(p) * sum_{gt>0.5} exp(-p) - n_neg ) / 2
//
// FINAL CONFIGURATION (verified stable: body 44.45-44.61us @ 6.08-6.12 TB/s
// across independent runs; total 45.3-46.4us incl. harness replay overhead).
//
// Design-space findings (all measured on sm_100a):
//  - load mechanism: plain x1 grid-stride LDG.128 (__ldcs) beats LDG.128x2,
//    LDG.E.256, and cp.async pipelines (all regress or neutral) -> the
//    ~6.1 TB/s plateau is an SM<->L2 fabric ceiling, not an MLP limit.
//  - CTA shape: consolidation at constant 2048 thr/SM is the only positive
//    gradient: 1184x256=5.87, 592x512=5.96, 296x1024=6.08+ TB/s. 296x1024
//    (2 CTA/SM, one exact wave) is the endpoint (1024 = max block).
//  - fused last-block fp64 combine: deterministic, sub-us epilogue.
//
// Deterministic (fixed-order fp64 final combine in last-arriving block),
// graph-capturable, allocation-free.
// ---------------------------------------------------------------------------

#define NBLOCKS 296
#define NTHREADS 1024

__device__ double g_part[3 * NBLOCKS];
__device__ unsigned int g_done = 0;   // self-resetting arrival counter

__device__ __forceinline__ void accum_one(float p, float g, float& s_neg,
                                          float& s_pos, float& cnt) {
    bool pos = g > 0.5f;
    float e = __expf(pos ? -p : p);
    if (pos) s_pos += e;
    else { s_neg += e; cnt += 1.0f; }
}

// Reduce three values across the block; results valid on (warp 0, lane 0).
template <typename T>
__device__ __forceinline__ void block_reduce3(T& a, T& b, T& c, T* sh) {
    int lane = threadIdx.x & 31;
    int warp = threadIdx.x >> 5;
    const int nw = NTHREADS / 32;

    #pragma unroll
    for (int off = 16; off > 0; off >>= 1) {
        a += __shfl_down_sync(0xffffffffu, a, off);
        b += __shfl_down_sync(0xffffffffu, b, off);
        c += __shfl_down_sync(0xffffffffu, c, off);
    }
    if (lane == 0) { sh[warp] = a; sh[nw + warp] = b; sh[2 * nw + warp] = c; }
    __syncthreads();
    if (warp == 0) {
        a = (lane < nw) ? sh[lane] : (T)0;
        b = (lane < nw) ? sh[nw + lane] : (T)0;
        c = (lane < nw) ? sh[2 * nw + lane] : (T)0;
        #pragma unroll
        for (int off = 16; off > 0; off >>= 1) {
            a += __shfl_down_sync(0xffffffffu, a, off);
            b += __shfl_down_sync(0xffffffffu, b, off);
            c += __shfl_down_sync(0xffffffffu, c, off);
        }
    }
}

__device__ __forceinline__ void epilogue(float s_neg, float s_pos, float cnt,
                                         float* __restrict__ out) {
    __shared__ float shf[3 * (NTHREADS / 32)];
    block_reduce3(s_neg, s_pos, cnt, shf);

    __shared__ bool s_last;
    if (threadIdx.x == 0) {
        g_part[blockIdx.x]               = (double)s_neg;
        g_part[NBLOCKS + blockIdx.x]     = (double)s_pos;
        g_part[2 * NBLOCKS + blockIdx.x] = (double)cnt;
        __threadfence();
        unsigned int prev = atomicAdd(&g_done, 1u);
        s_last = (prev == (unsigned int)(gridDim.x - 1));
    }
    __syncthreads();

    if (s_last) {
        __threadfence();  // acquire: all blocks' partials now visible
        // 296 partials x3: single strided read per thread; L2-hot.
        double a = 0.0, b = 0.0, c = 0.0;
        for (int k = threadIdx.x; k < NBLOCKS; k += NTHREADS) {
            a += g_part[k];
            b += g_part[NBLOCKS + k];
            c += g_part[2 * NBLOCKS + k];
        }
        __shared__ double shd[3 * (NTHREADS / 32)];
        block_reduce3(a, b, c, shd);
        if (threadIdx.x == 0) {
            out[0] = (float)((a * b - c) * 0.5);
            g_done = 0;  // reset for next graph replay
        }
    }
}

__global__ void __launch_bounds__(NTHREADS)
pairloss_stream(const float4* __restrict__ p4, const float4* __restrict__ g4,
                const float* __restrict__ pred, const float* __restrict__ gt,
                int n, float* __restrict__ out) {
    float s_neg = 0.0f, s_pos = 0.0f, cnt = 0.0f;
    const int n4 = n >> 2;
    const int stride = gridDim.x * blockDim.x;

    // x1 grid-stride, streaming loads (evict-first; one-touch data).
    for (int i = blockIdx.x * blockDim.x + threadIdx.x; i < n4; i += stride) {
        float4 p = __ldcs(p4 + i);
        float4 g = __ldcs(g4 + i);
        accum_one(p.x, g.x, s_neg, s_pos, cnt);
        accum_one(p.y, g.y, s_neg, s_pos, cnt);
        accum_one(p.z, g.z, s_neg, s_pos, cnt);
        accum_one(p.w, g.w, s_neg, s_pos, cnt);
    }
    // scalar tail (n % 4)
    for (int t = (n4 << 2) + blockIdx.x * blockDim.x + threadIdx.x; t < n;
         t += stride) {
        accum_one(__ldcs(pred + t), __ldcs(gt + t), s_neg, s_pos, cnt);
    }

    epilogue(s_neg, s_pos, cnt, out);
}

// Scalar fallback for unaligned inputs (not expected from the harness).
__global__ void __launch_bounds__(NTHREADS)
pairloss_scalar(const float* __restrict__ pred, const float* __restrict__ gt,
                int n, float* __restrict__ out) {
    float s_neg = 0.0f, s_pos = 0.0f, cnt = 0.0f;
    int stride = gridDim.x * blockDim.x;
    for (int i = blockIdx.x * blockDim.x + threadIdx.x; i < n; i += stride)
        accum_one(pred[i], gt[i], s_neg, s_pos, cnt);
    epilogue(s_neg, s_pos, cnt, out);
}

extern "C" void kernel_launch(void* const* d_in, const int* in_sizes, int n_in,
                              void* d_out, int out_size) {
    const float* pred = (const float*)d_in[0];
    const float* gt   = (const float*)d_in[1];
    float* out = (float*)d_out;
    int n = in_sizes[0];

    bool aligned = (((uintptr_t)pred | (uintptr_t)gt) & 0xF) == 0;
    if (aligned) {
        pairloss_stream<<<NBLOCKS, NTHREADS>>>(
            (const float4*)pred, (const float4*)gt, pred, gt, n, out);
    } else {
        pairloss_scalar<<<NBLOCKS, NTHREADS>>>(pred, gt, n, out);
    }
}